// round 1
// baseline (speedup 1.0000x reference)
#include <cuda_runtime.h>
#include <math.h>

#define NN 10000
#define NE 160000
#define HID 128
#define EMB 64
#define ITERS 16

// Scratch (device globals; no allocations allowed)
__device__ __align__(16) float g_h[NN * EMB];
__device__ __align__(16) float g_A[NN * HID];
__device__ __align__(16) float g_B[NN * HID];
__device__ __align__(16) float g_agg[NN * EMB];

// ---------------------------------------------------------------------------
// K_init: h = relu(relu(nf @ iw1 + ib1) @ iw2 + ib2)
// 128 threads, 16 nodes per block, 625 blocks.
// ---------------------------------------------------------------------------
__global__ void k_init(const float* __restrict__ nf,
                       const float* __restrict__ w1, const float* __restrict__ b1,
                       const float* __restrict__ w2, const float* __restrict__ b2) {
    __shared__ float w1s[2 * 128];
    __shared__ float b1s[128];
    __shared__ float w2s[128 * 64];
    __shared__ float b2s[64];
    __shared__ float hidS[16 * 132];

    int tid = threadIdx.x;
    int n0 = blockIdx.x * 16;

    if (tid < 256) w1s[tid] = w1[tid];
    w1s[tid + 128] = w1[tid + 128];  // tid<128 covers 0..255 with the line above? keep both safe
    if (tid < 128) { w1s[tid] = w1[tid]; w1s[128 + tid] = w1[128 + tid]; b1s[tid] = b1[tid]; }
    if (tid < 64) b2s[tid] = b2[tid];
    for (int idx = tid; idx < 128 * 64; idx += 128) w2s[idx] = w2[idx];
    __syncthreads();

    // stage 1: hid for 16 nodes; iteration it == node, all 128 threads = cols
    for (int it = 0; it < 16; it++) {
        int n = n0 + it;
        float f0 = nf[n * 2 + 0];
        float f1 = nf[n * 2 + 1];
        float v = fmaf(f0, w1s[tid], fmaf(f1, w1s[128 + tid], b1s[tid]));
        hidS[it * 132 + tid] = fmaxf(v, 0.f);
    }
    __syncthreads();

    // stage 2: 16 nodes x 64 cols = 1024 outputs, 8 per thread
    int node = tid >> 3;          // 0..15
    int c0 = (tid & 7) * 8;       // 0..56
    float acc[8];
#pragma unroll
    for (int j = 0; j < 8; j++) acc[j] = b2s[c0 + j];
    for (int k = 0; k < 128; k++) {
        float hv = hidS[node * 132 + k];
#pragma unroll
        for (int j = 0; j < 8; j++) acc[j] = fmaf(hv, w2s[k * 64 + c0 + j], acc[j]);
    }
    int n = n0 + node;
#pragma unroll
    for (int j = 0; j < 8; j++) g_h[n * 64 + c0 + j] = fmaxf(acc[j], 0.f);
}

// ---------------------------------------------------------------------------
// K_pre: out[n][0:OC] = [nf[n], h[n]] (66) @ Ws(66 x OC) (+ bias)
// Ws rows are contiguous in wsrc (row stride == OC for both edge_w1 halves
// and cls_w1 halves). Optionally zeros g_agg for this node tile.
// 256 threads, 32 nodes per block, 313 blocks.
// ---------------------------------------------------------------------------
template <int OC, bool ZERO_AGG>
__global__ void k_pre(const float* __restrict__ nf,
                      const float* __restrict__ wsrc,
                      const float* __restrict__ bias,
                      const float* __restrict__ h,
                      float* __restrict__ out,
                      float* __restrict__ agg) {
    __shared__ float Ws[66 * OC];
    __shared__ float xS[32 * 68];
    __shared__ float bS[OC];

    int tid = threadIdx.x;
    int n0 = blockIdx.x * 32;

    for (int idx = tid; idx < 66 * OC; idx += 256) Ws[idx] = wsrc[idx];
    for (int idx = tid; idx < OC; idx += 256) bS[idx] = bias ? bias[idx] : 0.f;
    if (ZERO_AGG) {
        for (int idx = tid; idx < 32 * 64; idx += 256) {
            int n = n0 + (idx >> 6);
            if (n < NN) agg[n * 64 + (idx & 63)] = 0.f;
        }
    }
    for (int idx = tid; idx < 32 * 64; idx += 256) {
        int i = idx >> 6, k = idx & 63;
        int n = n0 + i;
        xS[i * 68 + 2 + k] = (n < NN) ? h[n * 64 + k] : 0.f;
    }
    if (tid < 64) {
        int i = tid >> 1, f = tid & 1;
        int n = n0 + i;
        xS[i * 68 + f] = (n < NN) ? nf[n * 2 + f] : 0.f;
    }
    __syncthreads();

    constexpr int CJ = OC / 32;   // cols per thread (4 for OC=128, 2 for OC=64)
    int tn = (tid >> 5) * 4;      // node base (warp-uniform)
    int c0 = (tid & 31) * CJ;

    float acc[4][CJ];
#pragma unroll
    for (int i = 0; i < 4; i++)
#pragma unroll
        for (int j = 0; j < CJ; j++) acc[i][j] = bS[c0 + j];

#pragma unroll 2
    for (int k = 0; k < 66; k++) {
        float xv[4];
#pragma unroll
        for (int i = 0; i < 4; i++) xv[i] = xS[(tn + i) * 68 + k];
#pragma unroll
        for (int j = 0; j < CJ; j++) {
            float w = Ws[k * OC + c0 + j];
#pragma unroll
            for (int i = 0; i < 4; i++) acc[i][j] = fmaf(xv[i], w, acc[i][j]);
        }
    }
#pragma unroll
    for (int i = 0; i < 4; i++) {
        int n = n0 + tn + i;
        if (n < NN) {
#pragma unroll
            for (int j = 0; j < CJ; j++) out[n * OC + c0 + j] = acc[i][j];
        }
    }
}

// ---------------------------------------------------------------------------
// K_edge (hot): per edge e: hid = relu(A[dst] + B[src] + d*W1row132)  (128)
//               e_h = relu(hid @ W2 + b2)  (64); atomic agg[dst] += e_h
// 256 threads, 64 edges per block, 2500 blocks. Dynamic smem 66.5 KB.
// ---------------------------------------------------------------------------
__global__ void k_edge(const float* __restrict__ A, const float* __restrict__ B,
                       const float* __restrict__ dist,
                       const int* __restrict__ src, const int* __restrict__ dst,
                       const float* __restrict__ w2, const float* __restrict__ b2,
                       const float* __restrict__ w132,
                       float* __restrict__ agg) {
    extern __shared__ float sm[];
    float* W2s = sm;               // 128*64 = 8192
    float* hidS = sm + 8192;       // 64 rows, stride 132
    __shared__ float b2s[64];
    __shared__ __align__(16) float w132s[128];
    __shared__ int dstS[64];
    __shared__ int srcS[64];
    __shared__ float dS[64];

    int tid = threadIdx.x;
    int e0 = blockIdx.x * 64;

    for (int idx = tid; idx < 8192; idx += 256) W2s[idx] = w2[idx];
    if (tid < 64) b2s[tid] = b2[tid];
    if (tid < 128) w132s[tid] = w132[tid];
    if (tid < 64) {
        dstS[tid] = dst[e0 + tid];
        srcS[tid] = src[e0 + tid];
        dS[tid] = dist[e0 + tid];
    }
    __syncthreads();

    const float4* A4 = (const float4*)A;
    const float4* B4 = (const float4*)B;
    const float4* w4 = (const float4*)w132s;

    // stage A: build 64x128 hid tile
#pragma unroll
    for (int it = 0; it < 8; it++) {
        int idx = it * 256 + tid;
        int e = idx >> 5, q = idx & 31;
        float4 a = A4[dstS[e] * 32 + q];
        float4 b = B4[srcS[e] * 32 + q];
        float4 w = w4[q];
        float d = dS[e];
        float4 hv;
        hv.x = fmaxf(fmaf(d, w.x, a.x + b.x), 0.f);
        hv.y = fmaxf(fmaf(d, w.y, a.y + b.y), 0.f);
        hv.z = fmaxf(fmaf(d, w.z, a.z + b.z), 0.f);
        hv.w = fmaxf(fmaf(d, w.w, a.w + b.w), 0.f);
        *(float4*)(hidS + e * 132 + q * 4) = hv;
    }
    __syncthreads();

    // stage B: (64x128) @ (128x64); 16 outputs per thread (4 edges x 4 cols)
    int te = (tid >> 4) * 4;
    int c0 = (tid & 15) * 4;
    float acc[4][4];
#pragma unroll
    for (int i = 0; i < 4; i++) {
        acc[i][0] = b2s[c0 + 0]; acc[i][1] = b2s[c0 + 1];
        acc[i][2] = b2s[c0 + 2]; acc[i][3] = b2s[c0 + 3];
    }
#pragma unroll 4
    for (int k = 0; k < 128; k++) {
        float4 w = *(const float4*)(W2s + k * 64 + c0);
#pragma unroll
        for (int i = 0; i < 4; i++) {
            float hv = hidS[(te + i) * 132 + k];
            acc[i][0] = fmaf(hv, w.x, acc[i][0]);
            acc[i][1] = fmaf(hv, w.y, acc[i][1]);
            acc[i][2] = fmaf(hv, w.z, acc[i][2]);
            acc[i][3] = fmaf(hv, w.w, acc[i][3]);
        }
    }
#pragma unroll
    for (int i = 0; i < 4; i++) {
        float* ag = agg + dstS[te + i] * 64 + c0;
#pragma unroll
        for (int j = 0; j < 4; j++) atomicAdd(ag + j, fmaxf(acc[i][j], 0.f));
    }
}

// ---------------------------------------------------------------------------
// K_node: h = relu(relu([h, nf, agg] (130) @ nw1 + nb1) @ nw2 + nb2), in place
// 256 threads, 32 nodes per block, 313 blocks. Dynamic smem 133 KB.
// ---------------------------------------------------------------------------
__global__ void k_node(const float* __restrict__ nf,
                       float* __restrict__ h,
                       const float* __restrict__ agg,
                       const float* __restrict__ w1, const float* __restrict__ b1,
                       const float* __restrict__ w2, const float* __restrict__ b2) {
    extern __shared__ float sm[];
    float* W1s = sm;                 // 130*128 = 16640
    float* W2s = W1s + 16640;        // 8192
    float* xS = W2s + 8192;          // 32 x 132
    float* hidS = xS + 32 * 132;     // 32 x 132
    __shared__ float b1s[128];
    __shared__ float b2s[64];

    int tid = threadIdx.x;
    int n0 = blockIdx.x * 32;

    for (int idx = tid; idx < 16640; idx += 256) W1s[idx] = w1[idx];
    for (int idx = tid; idx < 8192; idx += 256) W2s[idx] = w2[idx];
    if (tid < 128) b1s[tid] = b1[tid];
    if (tid < 64) b2s[tid] = b2[tid];

    for (int idx = tid; idx < 32 * 64; idx += 256) {
        int i = idx >> 6, k = idx & 63;
        int n = n0 + i;
        float hv = 0.f, av = 0.f;
        if (n < NN) { hv = h[n * 64 + k]; av = agg[n * 64 + k]; }
        xS[i * 132 + k] = hv;            // rows 0..63: h
        xS[i * 132 + 66 + k] = av;       // rows 66..129: agg
    }
    if (tid < 64) {
        int i = tid >> 1, f = tid & 1;
        int n = n0 + i;
        xS[i * 132 + 64 + f] = (n < NN) ? nf[n * 2 + f] : 0.f;  // rows 64..65: nf
    }
    __syncthreads();

    // layer 1: 32x130 @ 130x128
    {
        int tn = (tid >> 5) * 4;
        int c0 = (tid & 31) * 4;
        float acc[4][4];
#pragma unroll
        for (int i = 0; i < 4; i++)
#pragma unroll
            for (int j = 0; j < 4; j++) acc[i][j] = b1s[c0 + j];
#pragma unroll 2
        for (int k = 0; k < 130; k++) {
            float4 w = *(const float4*)(W1s + k * 128 + c0);
#pragma unroll
            for (int i = 0; i < 4; i++) {
                float xv = xS[(tn + i) * 132 + k];
                acc[i][0] = fmaf(xv, w.x, acc[i][0]);
                acc[i][1] = fmaf(xv, w.y, acc[i][1]);
                acc[i][2] = fmaf(xv, w.z, acc[i][2]);
                acc[i][3] = fmaf(xv, w.w, acc[i][3]);
            }
        }
#pragma unroll
        for (int i = 0; i < 4; i++)
#pragma unroll
            for (int j = 0; j < 4; j++)
                hidS[(tn + i) * 132 + c0 + j] = fmaxf(acc[i][j], 0.f);
    }
    __syncthreads();

    // layer 2: 32x128 @ 128x64
    {
        int tn = (tid >> 5) * 4;
        int c0 = (tid & 31) * 2;
        float acc[4][2];
#pragma unroll
        for (int i = 0; i < 4; i++) { acc[i][0] = b2s[c0]; acc[i][1] = b2s[c0 + 1]; }
#pragma unroll 4
        for (int k = 0; k < 128; k++) {
            float2 w = *(const float2*)(W2s + k * 64 + c0);
#pragma unroll
            for (int i = 0; i < 4; i++) {
                float hv = hidS[(tn + i) * 132 + k];
                acc[i][0] = fmaf(hv, w.x, acc[i][0]);
                acc[i][1] = fmaf(hv, w.y, acc[i][1]);
            }
        }
#pragma unroll
        for (int i = 0; i < 4; i++) {
            int n = n0 + tn + i;
            if (n < NN) {
                h[n * 64 + c0 + 0] = fmaxf(acc[i][0], 0.f);
                h[n * 64 + c0 + 1] = fmaxf(acc[i][1], 0.f);
            }
        }
    }
}

// ---------------------------------------------------------------------------
// K_cls: per edge: m = relu(Ac[dst] + Bc[src] + d*w132c)  (64)
//        out[e] = sigmoid(m . cls_w2 + cls_b2)
// one warp per 8 edges; 256 threads, 2500 blocks.
// ---------------------------------------------------------------------------
__global__ void k_cls(const float* __restrict__ Ac, const float* __restrict__ Bc,
                      const float* __restrict__ dist,
                      const int* __restrict__ src, const int* __restrict__ dst,
                      const float* __restrict__ w132c,
                      const float* __restrict__ w2, const float* __restrict__ b2,
                      float* __restrict__ out) {
    __shared__ float w2s[64];
    __shared__ float w1s[64];
    int tid = threadIdx.x;
    if (tid < 64) { w2s[tid] = w2[tid]; w1s[tid] = w132c[tid]; }
    __syncthreads();

    int warp = tid >> 5, lane = tid & 31;
    float b2v = b2[0];
    int ebase = blockIdx.x * 64 + warp * 8;
#pragma unroll
    for (int i = 0; i < 8; i++) {
        int e = ebase + i;
        int dn = dst[e], sn = src[e];
        float d = dist[e];
        float m1 = fmaxf(fmaf(d, w1s[lane], Ac[dn * 64 + lane] + Bc[sn * 64 + lane]), 0.f);
        float m2 = fmaxf(fmaf(d, w1s[lane + 32], Ac[dn * 64 + lane + 32] + Bc[sn * 64 + lane + 32]), 0.f);
        float p = fmaf(m1, w2s[lane], m2 * w2s[lane + 32]);
#pragma unroll
        for (int o = 16; o; o >>= 1) p += __shfl_down_sync(0xffffffffu, p, o);
        if (lane == 0) out[e] = 1.f / (1.f + expf(-(p + b2v)));
    }
}

// ---------------------------------------------------------------------------

extern "C" void kernel_launch(void* const* d_in, const int* in_sizes, int n_in,
                              void* d_out, int out_size) {
    const float* nf   = (const float*)d_in[0];
    const float* dist = (const float*)d_in[1];
    const int*   src  = (const int*)d_in[2];
    const int*   dst  = (const int*)d_in[3];
    const float* iw1 = (const float*)d_in[4];
    const float* ib1 = (const float*)d_in[5];
    const float* iw2 = (const float*)d_in[6];
    const float* ib2 = (const float*)d_in[7];
    const float* ew1 = (const float*)d_in[8];
    const float* eb1 = (const float*)d_in[9];
    const float* ew2 = (const float*)d_in[10];
    const float* eb2 = (const float*)d_in[11];
    const float* nw1 = (const float*)d_in[12];
    const float* nb1 = (const float*)d_in[13];
    const float* nw2 = (const float*)d_in[14];
    const float* nb2 = (const float*)d_in[15];
    const float* cw1 = (const float*)d_in[16];
    const float* cb1 = (const float*)d_in[17];
    const float* cw2 = (const float*)d_in[18];
    const float* cb2 = (const float*)d_in[19];
    float* out = (float*)d_out;

    float *pA, *pB, *pAgg, *pH;
    cudaGetSymbolAddress((void**)&pA, g_A);
    cudaGetSymbolAddress((void**)&pB, g_B);
    cudaGetSymbolAddress((void**)&pAgg, g_agg);
    cudaGetSymbolAddress((void**)&pH, g_h);

    const int EDGE_SMEM = (8192 + 64 * 132) * 4;                       // 66560
    const int NODE_SMEM = (16640 + 8192 + 32 * 132 + 32 * 132) * 4;    // 133120
    cudaFuncSetAttribute(k_edge, cudaFuncAttributeMaxDynamicSharedMemorySize, EDGE_SMEM);
    cudaFuncSetAttribute(k_node, cudaFuncAttributeMaxDynamicSharedMemorySize, NODE_SMEM);

    const int PRE_BLOCKS = (NN + 31) / 32;   // 313
    const int EDGE_BLOCKS = NE / 64;         // 2500

    k_init<<<NN / 16, 128>>>(nf, iw1, ib1, iw2, ib2);

    for (int it = 0; it < ITERS; it++) {
        k_pre<128, true ><<<PRE_BLOCKS, 256>>>(nf, ew1,            eb1,     pH, pA, pAgg);
        k_pre<128, false><<<PRE_BLOCKS, 256>>>(nf, ew1 + 66 * 128, nullptr, pH, pB, nullptr);
        k_edge<<<EDGE_BLOCKS, 256, EDGE_SMEM>>>(pA, pB, dist, src, dst,
                                                ew2, eb2, ew1 + 132 * 128, pAgg);
        k_node<<<PRE_BLOCKS, 256, NODE_SMEM>>>(nf, pH, pAgg, nw1, nb1, nw2, nb2);
    }

    k_pre<64, false><<<PRE_BLOCKS, 256>>>(nf, cw1,           cb1,     pH, pA, nullptr);
    k_pre<64, false><<<PRE_BLOCKS, 256>>>(nf, cw1 + 66 * 64, nullptr, pH, pB, nullptr);
    k_cls<<<EDGE_BLOCKS, 256>>>(pA, pB, dist, src, dst,
                                cw1 + 132 * 64, cw2, cb2, out);
}